// round 9
// baseline (speedup 1.0000x reference)
#include <cuda_runtime.h>
#include <cuda_bf16.h>
#include <cstddef>

// ---------------------------------------------------------------------------
// MS-SSIM, 32x1x512x512 fp32 pairs, 5 levels, 11x11 Gaussian (sigma=1.5).
// ssim_all works entirely in the (s,d) = (u+v, u-v) basis, packed f32x2:
//   blur(s), blur(d)      -> ms = mu1+mu2, md = mu1-mu2
//   blur(s^2), blur(d^2)  -> P, Q
//   2*mu1*mu2     = (ms^2 - md^2)/2       mu1^2+mu2^2 = (ms^2 + md^2)/2
//   2*sigma12+..  = (P-Q)/2 - (ms^2-md^2)/2
//   sigma1+sigma2 = (P+Q)/2 - (ms^2+md^2)/2
// Inner blur iteration: 1 LDS.64 + 1 mul2 + 2 fma2 per tap. No packs/adds.
// ---------------------------------------------------------------------------

#define TILE  32
#define HALO  5
#define SROWS (TILE + 2*HALO)   // 42
#define SSTR  43                // sSD row stride (u64 units)
#define HSTR  33                // hb row stride (u64 units)
#define WIN   11

typedef unsigned long long u64;

#define GW0 0.00102839f
#define GW1 0.00759870f
#define GW2 0.03600080f
#define GW3 0.10936070f
#define GW4 0.21300540f
#define GW5 0.26601170f

#define C1F 1.0e-4f   // 0.01^2
#define C2F 9.0e-4f   // 0.03^2

#define OFF1 ((size_t)0)
#define OFF2 (OFF1 + (size_t)32 * 256 * 256)
#define OFF3 (OFF2 + (size_t)32 * 128 * 128)
#define OFF4 (OFF3 + (size_t)32 * 64 * 64)

__device__ float g_buf1[32u * 87040u];
__device__ float g_buf2[32u * 87040u];
__device__ double g_sums[10];

// ---- f32x2 packed helpers -------------------------------------------------
__device__ __forceinline__ void fma2(u64& d, u64 a, u64 b) {
    asm("fma.rn.f32x2 %0, %1, %2, %0;" : "+l"(d) : "l"(a), "l"(b));
}
__device__ __forceinline__ u64 mul2(u64 a, u64 b) {
    u64 r;
    asm("mul.rn.f32x2 %0, %1, %2;" : "=l"(r) : "l"(a), "l"(b));
    return r;
}
__device__ __forceinline__ u64 pack2(float x, float y) {
    u64 r;
    asm("mov.b64 %0, {%1, %2};" : "=l"(r) : "f"(x), "f"(y));
    return r;
}
__device__ __forceinline__ float lo32(u64 a) {
    float r;
    asm("{ .reg .f32 hi; mov.b64 {%0, hi}, %1; }" : "=f"(r) : "l"(a));
    return r;
}
__device__ __forceinline__ float hi32(u64 a) {
    float r;
    asm("{ .reg .f32 lo; mov.b64 {lo, %0}, %1; }" : "=f"(r) : "l"(a));
    return r;
}

// ---------------------------------------------------------------------------
// Pyramid builder: grid (8, 8, 32), block 256. (DRAM-bound ~15us; unchanged)
// ---------------------------------------------------------------------------
__global__ __launch_bounds__(256)
void pyramid_kernel(const float* __restrict__ img1,
                    const float* __restrict__ img2,
                    float* __restrict__ buf1,
                    float* __restrict__ buf2,
                    double* __restrict__ sums)
{
    __shared__ float a1[32][33], a2[32][33];
    __shared__ float e1[16][17], e2[16][17];
    __shared__ float c1[8][9],  c2[8][9];

    const int tid = threadIdx.x;
    const int bx = blockIdx.x, by = blockIdx.y, b = blockIdx.z;

    if (bx == 0 && by == 0 && b == 0 && tid < 10) sums[tid] = 0.0;

    const float* __restrict__ p1 = img1 + (size_t)b * 512 * 512;
    const float* __restrict__ p2 = img2 + (size_t)b * 512 * 512;

#pragma unroll
    for (int it = 0; it < 4; it++) {
        const int o  = tid + 256 * it;
        const int oy = o >> 5, ox = o & 31;
        const size_t r0 = (size_t)(by * 64 + 2 * oy) * 512 + bx * 64 + 2 * ox;
        const float2 u0 = *(const float2*)(p1 + r0);
        const float2 u1 = *(const float2*)(p1 + r0 + 512);
        const float2 v0 = *(const float2*)(p2 + r0);
        const float2 v1 = *(const float2*)(p2 + r0 + 512);
        const float d1 = 0.25f * (u0.x + u0.y + u1.x + u1.y);
        const float d2 = 0.25f * (v0.x + v0.y + v1.x + v1.y);
        a1[oy][ox] = d1;
        a2[oy][ox] = d2;
        const size_t gi = ((size_t)b * 256 + (by * 32 + oy)) * 256 + (bx * 32 + ox);
        buf1[OFF1 + gi] = d1;
        buf2[OFF1 + gi] = d2;
    }
    __syncthreads();

    {
        const int oy = tid >> 4, ox = tid & 15;
        const float d1 = 0.25f * (a1[2*oy][2*ox] + a1[2*oy][2*ox+1] +
                                  a1[2*oy+1][2*ox] + a1[2*oy+1][2*ox+1]);
        const float d2 = 0.25f * (a2[2*oy][2*ox] + a2[2*oy][2*ox+1] +
                                  a2[2*oy+1][2*ox] + a2[2*oy+1][2*ox+1]);
        e1[oy][ox] = d1;
        e2[oy][ox] = d2;
        const size_t gi = ((size_t)b * 128 + (by * 16 + oy)) * 128 + (bx * 16 + ox);
        buf1[OFF2 + gi] = d1;
        buf2[OFF2 + gi] = d2;
    }
    __syncthreads();

    if (tid < 64) {
        const int oy = tid >> 3, ox = tid & 7;
        const float d1 = 0.25f * (e1[2*oy][2*ox] + e1[2*oy][2*ox+1] +
                                  e1[2*oy+1][2*ox] + e1[2*oy+1][2*ox+1]);
        const float d2 = 0.25f * (e2[2*oy][2*ox] + e2[2*oy][2*ox+1] +
                                  e2[2*oy+1][2*ox] + e2[2*oy+1][2*ox+1]);
        c1[oy][ox] = d1;
        c2[oy][ox] = d2;
        const size_t gi = ((size_t)b * 64 + (by * 8 + oy)) * 64 + (bx * 8 + ox);
        buf1[OFF3 + gi] = d1;
        buf2[OFF3 + gi] = d2;
    }
    __syncthreads();

    if (tid < 16) {
        const int oy = tid >> 2, ox = tid & 3;
        const float d1 = 0.25f * (c1[2*oy][2*ox] + c1[2*oy][2*ox+1] +
                                  c1[2*oy+1][2*ox] + c1[2*oy+1][2*ox+1]);
        const float d2 = 0.25f * (c2[2*oy][2*ox] + c2[2*oy][2*ox+1] +
                                  c2[2*oy+1][2*ox] + c2[2*oy+1][2*ox+1]);
        const size_t gi = ((size_t)b * 32 + (by * 4 + oy)) * 32 + (bx * 4 + ox);
        buf1[OFF4 + gi] = d1;
        buf2[OFF4 + gi] = d2;
    }
}

// ---------------------------------------------------------------------------
// All 5 SSIM levels, one flat grid. Block (32,8), 6 blocks/SM.
// (s,d) basis throughout; 4 packed moment fields in 2 u64 lanes.
// ---------------------------------------------------------------------------
__global__ __launch_bounds__(256, 6)
void ssim_all_kernel(const float* __restrict__ img1,
                     const float* __restrict__ img2,
                     const float* __restrict__ buf1,
                     const float* __restrict__ buf2,
                     double* __restrict__ sums)
{
    __shared__ u64   sSD[SROWS][SSTR];      // packed (s, d)
    __shared__ u64   hbSD[SROWS][HSTR];     // (blur_h s, blur_h d)
    __shared__ u64   hbPQ[SROWS][HSTR];     // (blur_h s^2, blur_h d^2)
    __shared__ float wsum[8][2];

    const int tx  = threadIdx.x;
    const int ty  = threadIdx.y;
    const int tid = ty * 32 + tx;

    // 6 packed weight registers from immediates
    const u64 W0 = pack2(GW0, GW0);
    const u64 W1 = pack2(GW1, GW1);
    const u64 W2r = pack2(GW2, GW2);
    const u64 W3 = pack2(GW3, GW3);
    const u64 W4 = pack2(GW4, GW4);
    const u64 W5 = pack2(GW5, GW5);

#define WSEL(k) ((k) == 0 || (k) == 10 ? W0 : \
                 (k) == 1 || (k) == 9  ? W1 : \
                 (k) == 2 || (k) == 8  ? W2r : \
                 (k) == 3 || (k) == 7  ? W3 : \
                 (k) == 4 || (k) == 6  ? W4 : W5)

    // decode level + tile coordinates from flat block id
    const int gb = blockIdx.x;
    int level, start;
    const float *p1base, *p2base;
    if (gb < 8192)       { level = 0; start = 0;     p1base = img1;        p2base = img2;        }
    else if (gb < 10240) { level = 1; start = 8192;  p1base = buf1 + OFF1; p2base = buf2 + OFF1; }
    else if (gb < 10752) { level = 2; start = 10240; p1base = buf1 + OFF2; p2base = buf2 + OFF2; }
    else if (gb < 10880) { level = 3; start = 10752; p1base = buf1 + OFF3; p2base = buf2 + OFF3; }
    else                 { level = 4; start = 10880; p1base = buf1 + OFF4; p2base = buf2 + OFF4; }

    const int shift = 4 - level;
    const int nbx   = 1 << shift;
    const int H     = 512 >> level;
    const int idx   = gb - start;
    const int b     = idx >> (2 * shift);
    const int rem   = idx & ((1 << (2 * shift)) - 1);
    const int byi   = rem >> shift;
    const int bxi   = rem & (nbx - 1);

    const int x0 = bxi * TILE - HALO;
    const int y0 = byi * TILE - HALO;

    const float* __restrict__ p1 = p1base + (size_t)b * H * H;
    const float* __restrict__ p2 = p2base + (size_t)b * H * H;

    // ---- load 42x42 halo tile as packed (u+v, u-v); zero pad = SAME ----
    const bool interior = (x0 >= 0) && (y0 >= 0) &&
                          (x0 + SROWS <= H) && (y0 + SROWS <= H);
    if (interior) {
        for (int r = ty; r < SROWS; r += 8) {
            const size_t row = (size_t)(y0 + r) * H + x0;
#pragma unroll
            for (int c = tx; c < SROWS; c += TILE) {
                const float u = p1[row + c];
                const float v = p2[row + c];
                sSD[r][c] = pack2(u + v, u - v);
            }
        }
    } else {
        for (int r = ty; r < SROWS; r += 8) {
            const int gy = y0 + r;
            const bool yok = (gy >= 0) && (gy < H);
#pragma unroll
            for (int c = tx; c < SROWS; c += TILE) {
                const int gx = x0 + c;
                float u = 0.f, v = 0.f;
                if (yok && gx >= 0 && gx < H) {
                    u = p1[(size_t)gy * H + gx];
                    v = p2[(size_t)gy * H + gx];
                }
                sSD[r][c] = pack2(u + v, u - v);
            }
        }
    }
    __syncthreads();

    // ---- horizontal 11-tap pass: 42 rows x 8 col-groups of 4 ----
    for (int t = tid; t < SROWS * 8; t += 256) {
        const int r  = t >> 3;
        const int cg = (t & 7) << 2;
        const u64* __restrict__ srow = &sSD[r][cg];

        u64 ASD[4] = {0ull, 0ull, 0ull, 0ull};
        u64 APQ[4] = {0ull, 0ull, 0ull, 0ull};
#pragma unroll
        for (int i = 0; i < 14; i++) {
            const u64 sd = srow[i];              // one LDS.64
            const u64 sq = mul2(sd, sd);         // (s^2, d^2)
#pragma unroll
            for (int j = 0; j < 4; j++) {
                const int k = i - j;
                if (k >= 0 && k < WIN) {
                    fma2(ASD[j], WSEL(k), sd);
                    fma2(APQ[j], WSEL(k), sq);
                }
            }
        }
#pragma unroll
        for (int j = 0; j < 4; j++) {
            hbSD[r][cg + j] = ASD[j];
            hbPQ[r][cg + j] = APQ[j];
        }
    }
    __syncthreads();

    // ---- vertical 11-tap pass: thread = col tx, rows 4*ty .. 4*ty+3 ----
    u64 VSD[4] = {0ull, 0ull, 0ull, 0ull};
    u64 VPQ[4] = {0ull, 0ull, 0ull, 0ull};

    const int r0 = ty << 2;
#pragma unroll
    for (int i = 0; i < 14; i++) {
        const u64 hSD = hbSD[r0 + i][tx];        // LDS.64
        const u64 hPQ = hbPQ[r0 + i][tx];        // LDS.64
#pragma unroll
        for (int j = 0; j < 4; j++) {
            const int k = i - j;
            if (k >= 0 && k < WIN) {
                fma2(VSD[j], WSEL(k), hSD);
                fma2(VPQ[j], WSEL(k), hPQ);
            }
        }
    }
#undef WSEL

    float lssim = 0.f, lmcs = 0.f;
#pragma unroll
    for (int j = 0; j < 4; j++) {
        const float ms = lo32(VSD[j]);           // mu1+mu2
        const float md = hi32(VSD[j]);           // mu1-mu2
        const float P  = lo32(VPQ[j]);           // blur((u+v)^2)
        const float Q  = hi32(VPQ[j]);           // blur((u-v)^2)
        const float S2 = ms * ms;
        const float D2 = md * md;
        const float a  = 0.5f * (S2 - D2);       // 2*mu1*mu2
        const float bb = 0.5f * (S2 + D2);       // mu1^2+mu2^2
        const float num2 = 0.5f * (P - Q) - a + C2F;   // 2*sigma12 + C2
        const float den2 = 0.5f * (P + Q) - bb + C2F;  // sigma1+sigma2 + C2
        const float mcs  = __fdividef(num2, den2);
        const float ssim = __fdividef(a + C1F, bb + C1F) * mcs;
        lssim += ssim;
        lmcs  += mcs;
    }

    // ---- block reduction + per-level double atomics ----
#pragma unroll
    for (int o = 16; o > 0; o >>= 1) {
        lssim += __shfl_down_sync(0xffffffffu, lssim, o);
        lmcs  += __shfl_down_sync(0xffffffffu, lmcs,  o);
    }
    if (tx == 0) {
        wsum[ty][0] = lssim;
        wsum[ty][1] = lmcs;
    }
    __syncthreads();
    if (ty == 0 && tx < 8) {
        float a = wsum[tx][0];
        float c = wsum[tx][1];
#pragma unroll
        for (int o = 4; o > 0; o >>= 1) {
            a += __shfl_down_sync(0xffu, a, o);
            c += __shfl_down_sync(0xffu, c, o);
        }
        if (tx == 0) {
            atomicAdd(&sums[2 * level + 0], (double)a);
            atomicAdd(&sums[2 * level + 1], (double)c);
        }
    }
}

__global__ void finalize_kernel(const double* __restrict__ sums,
                                float* __restrict__ out)
{
    const double w[5] = {0.0448, 0.2856, 0.3001, 0.2363, 0.1333};
    double res = 1.0;
#pragma unroll
    for (int l = 0; l < 4; l++) {
        const double dim = (double)(512 >> l);
        const double N = 32.0 * dim * dim;
        const double mcs = sums[2 * l + 1] / N;
        res *= pow(mcs, w[l]);
    }
    {
        const double N = 32.0 * 32.0 * 32.0;
        const double ssim = sums[2 * 4 + 0] / N;
        res *= pow(ssim, w[4]);
    }
    out[0] = (float)res;
}

extern "C" void kernel_launch(void* const* d_in, const int* in_sizes, int n_in,
                              void* d_out, int out_size)
{
    const float* img1 = (const float*)d_in[0];
    const float* img2 = (const float*)d_in[1];
    float* out = (float*)d_out;

    double* sums = nullptr;
    float*  buf1 = nullptr;
    float*  buf2 = nullptr;
    cudaGetSymbolAddress((void**)&sums, g_sums);
    cudaGetSymbolAddress((void**)&buf1, g_buf1);
    cudaGetSymbolAddress((void**)&buf2, g_buf2);

    pyramid_kernel<<<dim3(8, 8, 32), 256>>>(img1, img2, buf1, buf2, sums);
    ssim_all_kernel<<<10912, dim3(32, 8)>>>(img1, img2, buf1, buf2, sums);
    finalize_kernel<<<1, 1>>>(sums, out);
}

// round 10
// speedup vs baseline: 1.0568x; 1.0568x over previous
#include <cuda_runtime.h>
#include <cuda_bf16.h>
#include <cstddef>

// ---------------------------------------------------------------------------
// MS-SSIM, 32x1x512x512 fp32 pairs, 5 levels, 11x11 Gaussian (sigma=1.5).
// (s,d) = (u+v, u-v) basis, packed f32x2, 4 moment fields in 2 u64 lanes.
// Round 10: conflict-free h-pass task mapping (16 lanes = 4 rows x 4 groups).
// ---------------------------------------------------------------------------

#define TILE  32
#define HALO  5
#define SROWS (TILE + 2*HALO)   // 42
#define SSTR  43                // sSD row stride (u64 units)
#define HSTR  33                // hb row stride (u64 units)
#define WIN   11

typedef unsigned long long u64;

#define GW0 0.00102839f
#define GW1 0.00759870f
#define GW2 0.03600080f
#define GW3 0.10936070f
#define GW4 0.21300540f
#define GW5 0.26601170f

#define C1F 1.0e-4f   // 0.01^2
#define C2F 9.0e-4f   // 0.03^2

#define OFF1 ((size_t)0)
#define OFF2 (OFF1 + (size_t)32 * 256 * 256)
#define OFF3 (OFF2 + (size_t)32 * 128 * 128)
#define OFF4 (OFF3 + (size_t)32 * 64 * 64)

__device__ float g_buf1[32u * 87040u];
__device__ float g_buf2[32u * 87040u];
__device__ double g_sums[10];

// ---- f32x2 packed helpers -------------------------------------------------
__device__ __forceinline__ void fma2(u64& d, u64 a, u64 b) {
    asm("fma.rn.f32x2 %0, %1, %2, %0;" : "+l"(d) : "l"(a), "l"(b));
}
__device__ __forceinline__ u64 mul2(u64 a, u64 b) {
    u64 r;
    asm("mul.rn.f32x2 %0, %1, %2;" : "=l"(r) : "l"(a), "l"(b));
    return r;
}
__device__ __forceinline__ u64 pack2(float x, float y) {
    u64 r;
    asm("mov.b64 %0, {%1, %2};" : "=l"(r) : "f"(x), "f"(y));
    return r;
}
__device__ __forceinline__ float lo32(u64 a) {
    float r;
    asm("{ .reg .f32 hi; mov.b64 {%0, hi}, %1; }" : "=f"(r) : "l"(a));
    return r;
}
__device__ __forceinline__ float hi32(u64 a) {
    float r;
    asm("{ .reg .f32 lo; mov.b64 {lo, %0}, %1; }" : "=f"(r) : "l"(a));
    return r;
}

// ---------------------------------------------------------------------------
// Pyramid builder: grid (8, 8, 32), block 256. (DRAM-bound ~15us; unchanged)
// ---------------------------------------------------------------------------
__global__ __launch_bounds__(256)
void pyramid_kernel(const float* __restrict__ img1,
                    const float* __restrict__ img2,
                    float* __restrict__ buf1,
                    float* __restrict__ buf2,
                    double* __restrict__ sums)
{
    __shared__ float a1[32][33], a2[32][33];
    __shared__ float e1[16][17], e2[16][17];
    __shared__ float c1[8][9],  c2[8][9];

    const int tid = threadIdx.x;
    const int bx = blockIdx.x, by = blockIdx.y, b = blockIdx.z;

    if (bx == 0 && by == 0 && b == 0 && tid < 10) sums[tid] = 0.0;

    const float* __restrict__ p1 = img1 + (size_t)b * 512 * 512;
    const float* __restrict__ p2 = img2 + (size_t)b * 512 * 512;

#pragma unroll
    for (int it = 0; it < 4; it++) {
        const int o  = tid + 256 * it;
        const int oy = o >> 5, ox = o & 31;
        const size_t r0 = (size_t)(by * 64 + 2 * oy) * 512 + bx * 64 + 2 * ox;
        const float2 u0 = *(const float2*)(p1 + r0);
        const float2 u1 = *(const float2*)(p1 + r0 + 512);
        const float2 v0 = *(const float2*)(p2 + r0);
        const float2 v1 = *(const float2*)(p2 + r0 + 512);
        const float d1 = 0.25f * (u0.x + u0.y + u1.x + u1.y);
        const float d2 = 0.25f * (v0.x + v0.y + v1.x + v1.y);
        a1[oy][ox] = d1;
        a2[oy][ox] = d2;
        const size_t gi = ((size_t)b * 256 + (by * 32 + oy)) * 256 + (bx * 32 + ox);
        buf1[OFF1 + gi] = d1;
        buf2[OFF1 + gi] = d2;
    }
    __syncthreads();

    {
        const int oy = tid >> 4, ox = tid & 15;
        const float d1 = 0.25f * (a1[2*oy][2*ox] + a1[2*oy][2*ox+1] +
                                  a1[2*oy+1][2*ox] + a1[2*oy+1][2*ox+1]);
        const float d2 = 0.25f * (a2[2*oy][2*ox] + a2[2*oy][2*ox+1] +
                                  a2[2*oy+1][2*ox] + a2[2*oy+1][2*ox+1]);
        e1[oy][ox] = d1;
        e2[oy][ox] = d2;
        const size_t gi = ((size_t)b * 128 + (by * 16 + oy)) * 128 + (bx * 16 + ox);
        buf1[OFF2 + gi] = d1;
        buf2[OFF2 + gi] = d2;
    }
    __syncthreads();

    if (tid < 64) {
        const int oy = tid >> 3, ox = tid & 7;
        const float d1 = 0.25f * (e1[2*oy][2*ox] + e1[2*oy][2*ox+1] +
                                  e1[2*oy+1][2*ox] + e1[2*oy+1][2*ox+1]);
        const float d2 = 0.25f * (e2[2*oy][2*ox] + e2[2*oy][2*ox+1] +
                                  e2[2*oy+1][2*ox] + e2[2*oy+1][2*ox+1]);
        c1[oy][ox] = d1;
        c2[oy][ox] = d2;
        const size_t gi = ((size_t)b * 64 + (by * 8 + oy)) * 64 + (bx * 8 + ox);
        buf1[OFF3 + gi] = d1;
        buf2[OFF3 + gi] = d2;
    }
    __syncthreads();

    if (tid < 16) {
        const int oy = tid >> 2, ox = tid & 3;
        const float d1 = 0.25f * (c1[2*oy][2*ox] + c1[2*oy][2*ox+1] +
                                  c1[2*oy+1][2*ox] + c1[2*oy+1][2*ox+1]);
        const float d2 = 0.25f * (c2[2*oy][2*ox] + c2[2*oy][2*ox+1] +
                                  c2[2*oy+1][2*ox] + c2[2*oy+1][2*ox+1]);
        const size_t gi = ((size_t)b * 32 + (by * 4 + oy)) * 32 + (bx * 4 + ox);
        buf1[OFF4 + gi] = d1;
        buf2[OFF4 + gi] = d2;
    }
}

// ---------------------------------------------------------------------------
// All 5 SSIM levels, one flat grid. Block (32,8), 6 blocks/SM.
// ---------------------------------------------------------------------------
__global__ __launch_bounds__(256, 6)
void ssim_all_kernel(const float* __restrict__ img1,
                     const float* __restrict__ img2,
                     const float* __restrict__ buf1,
                     const float* __restrict__ buf2,
                     double* __restrict__ sums)
{
    __shared__ u64   sSD[SROWS][SSTR];      // packed (s, d)
    __shared__ u64   hbSD[SROWS][HSTR];     // (blur_h s, blur_h d)
    __shared__ u64   hbPQ[SROWS][HSTR];     // (blur_h s^2, blur_h d^2)
    __shared__ float wsum[8][2];

    const int tx  = threadIdx.x;
    const int ty  = threadIdx.y;
    const int tid = ty * 32 + tx;

    const u64 W0 = pack2(GW0, GW0);
    const u64 W1 = pack2(GW1, GW1);
    const u64 W2r = pack2(GW2, GW2);
    const u64 W3 = pack2(GW3, GW3);
    const u64 W4 = pack2(GW4, GW4);
    const u64 W5 = pack2(GW5, GW5);

#define WSEL(k) ((k) == 0 || (k) == 10 ? W0 : \
                 (k) == 1 || (k) == 9  ? W1 : \
                 (k) == 2 || (k) == 8  ? W2r : \
                 (k) == 3 || (k) == 7  ? W3 : \
                 (k) == 4 || (k) == 6  ? W4 : W5)

    // decode level + tile coordinates from flat block id
    const int gb = blockIdx.x;
    int level, start;
    const float *p1base, *p2base;
    if (gb < 8192)       { level = 0; start = 0;     p1base = img1;        p2base = img2;        }
    else if (gb < 10240) { level = 1; start = 8192;  p1base = buf1 + OFF1; p2base = buf2 + OFF1; }
    else if (gb < 10752) { level = 2; start = 10240; p1base = buf1 + OFF2; p2base = buf2 + OFF2; }
    else if (gb < 10880) { level = 3; start = 10752; p1base = buf1 + OFF3; p2base = buf2 + OFF3; }
    else                 { level = 4; start = 10880; p1base = buf1 + OFF4; p2base = buf2 + OFF4; }

    const int shift = 4 - level;
    const int nbx   = 1 << shift;
    const int H     = 512 >> level;
    const int idx   = gb - start;
    const int b     = idx >> (2 * shift);
    const int rem   = idx & ((1 << (2 * shift)) - 1);
    const int byi   = rem >> shift;
    const int bxi   = rem & (nbx - 1);

    const int x0 = bxi * TILE - HALO;
    const int y0 = byi * TILE - HALO;

    const float* __restrict__ p1 = p1base + (size_t)b * H * H;
    const float* __restrict__ p2 = p2base + (size_t)b * H * H;

    // ---- load 42x42 halo tile as packed (u+v, u-v); zero pad = SAME ----
    const bool interior = (x0 >= 0) && (y0 >= 0) &&
                          (x0 + SROWS <= H) && (y0 + SROWS <= H);
    if (interior) {
        for (int r = ty; r < SROWS; r += 8) {
            const size_t row = (size_t)(y0 + r) * H + x0;
#pragma unroll
            for (int c = tx; c < SROWS; c += TILE) {
                const float u = p1[row + c];
                const float v = p2[row + c];
                sSD[r][c] = pack2(u + v, u - v);
            }
        }
    } else {
        for (int r = ty; r < SROWS; r += 8) {
            const int gy = y0 + r;
            const bool yok = (gy >= 0) && (gy < H);
#pragma unroll
            for (int c = tx; c < SROWS; c += TILE) {
                const int gx = x0 + c;
                float u = 0.f, v = 0.f;
                if (yok && gx >= 0 && gx < H) {
                    u = p1[(size_t)gy * H + gx];
                    v = p2[(size_t)gy * H + gx];
                }
                sSD[r][c] = pack2(u + v, u - v);
            }
        }
    }
    __syncthreads();

    // ---- horizontal 11-tap pass, conflict-free mapping ----
    // task t -> cg4 = t&3 (col-group within half), rr = t>>2 (0..83),
    // r = rr mod 42, column-half = rr/42. 16 consecutive lanes cover
    // 4 rows x 4 col-groups -> all 16 bank-pairs distinct for both the
    // sSD reads (stride 86 words) and hb writes (stride 66 words).
    for (int t = tid; t < SROWS * 8; t += 256) {
        const int cg4  = t & 3;
        const int rr   = t >> 2;
        const int half = (rr >= SROWS) ? 1 : 0;
        const int r    = rr - half * SROWS;
        const int cg   = (cg4 + (half << 2)) << 2;
        const u64* __restrict__ srow = &sSD[r][cg];

        u64 ASD[4] = {0ull, 0ull, 0ull, 0ull};
        u64 APQ[4] = {0ull, 0ull, 0ull, 0ull};
#pragma unroll
        for (int i = 0; i < 14; i++) {
            const u64 sd = srow[i];              // LDS.64, conflict-free
            const u64 sq = mul2(sd, sd);         // (s^2, d^2)
#pragma unroll
            for (int j = 0; j < 4; j++) {
                const int k = i - j;
                if (k >= 0 && k < WIN) {
                    fma2(ASD[j], WSEL(k), sd);
                    fma2(APQ[j], WSEL(k), sq);
                }
            }
        }
#pragma unroll
        for (int j = 0; j < 4; j++) {
            hbSD[r][cg + j] = ASD[j];
            hbPQ[r][cg + j] = APQ[j];
        }
    }
    __syncthreads();

    // ---- vertical 11-tap pass: thread = col tx, rows 4*ty .. 4*ty+3 ----
    u64 VSD[4] = {0ull, 0ull, 0ull, 0ull};
    u64 VPQ[4] = {0ull, 0ull, 0ull, 0ull};

    const int r0 = ty << 2;
#pragma unroll
    for (int i = 0; i < 14; i++) {
        const u64 hSD = hbSD[r0 + i][tx];
        const u64 hPQ = hbPQ[r0 + i][tx];
#pragma unroll
        for (int j = 0; j < 4; j++) {
            const int k = i - j;
            if (k >= 0 && k < WIN) {
                fma2(VSD[j], WSEL(k), hSD);
                fma2(VPQ[j], WSEL(k), hPQ);
            }
        }
    }
#undef WSEL

    float lssim = 0.f, lmcs = 0.f;
#pragma unroll
    for (int j = 0; j < 4; j++) {
        const float ms = lo32(VSD[j]);           // mu1+mu2
        const float md = hi32(VSD[j]);           // mu1-mu2
        const float P  = lo32(VPQ[j]);           // blur((u+v)^2)
        const float Q  = hi32(VPQ[j]);           // blur((u-v)^2)
        const float S2 = ms * ms;
        const float D2 = md * md;
        const float a  = 0.5f * (S2 - D2);       // 2*mu1*mu2
        const float bb = 0.5f * (S2 + D2);       // mu1^2+mu2^2
        const float num2 = 0.5f * (P - Q) - a + C2F;   // 2*sigma12 + C2
        const float den2 = 0.5f * (P + Q) - bb + C2F;  // sigma1+sigma2 + C2
        const float mcs  = __fdividef(num2, den2);
        const float ssim = __fdividef(a + C1F, bb + C1F) * mcs;
        lssim += ssim;
        lmcs  += mcs;
    }

    // ---- block reduction + per-level double atomics ----
#pragma unroll
    for (int o = 16; o > 0; o >>= 1) {
        lssim += __shfl_down_sync(0xffffffffu, lssim, o);
        lmcs  += __shfl_down_sync(0xffffffffu, lmcs,  o);
    }
    if (tx == 0) {
        wsum[ty][0] = lssim;
        wsum[ty][1] = lmcs;
    }
    __syncthreads();
    if (ty == 0 && tx < 8) {
        float a = wsum[tx][0];
        float c = wsum[tx][1];
#pragma unroll
        for (int o = 4; o > 0; o >>= 1) {
            a += __shfl_down_sync(0xffu, a, o);
            c += __shfl_down_sync(0xffu, c, o);
        }
        if (tx == 0) {
            atomicAdd(&sums[2 * level + 0], (double)a);
            atomicAdd(&sums[2 * level + 1], (double)c);
        }
    }
}

__global__ void finalize_kernel(const double* __restrict__ sums,
                                float* __restrict__ out)
{
    const double w[5] = {0.0448, 0.2856, 0.3001, 0.2363, 0.1333};
    double res = 1.0;
#pragma unroll
    for (int l = 0; l < 4; l++) {
        const double dim = (double)(512 >> l);
        const double N = 32.0 * dim * dim;
        const double mcs = sums[2 * l + 1] / N;
        res *= pow(mcs, w[l]);
    }
    {
        const double N = 32.0 * 32.0 * 32.0;
        const double ssim = sums[2 * 4 + 0] / N;
        res *= pow(ssim, w[4]);
    }
    out[0] = (float)res;
}

extern "C" void kernel_launch(void* const* d_in, const int* in_sizes, int n_in,
                              void* d_out, int out_size)
{
    const float* img1 = (const float*)d_in[0];
    const float* img2 = (const float*)d_in[1];
    float* out = (float*)d_out;

    double* sums = nullptr;
    float*  buf1 = nullptr;
    float*  buf2 = nullptr;
    cudaGetSymbolAddress((void**)&sums, g_sums);
    cudaGetSymbolAddress((void**)&buf1, g_buf1);
    cudaGetSymbolAddress((void**)&buf2, g_buf2);

    pyramid_kernel<<<dim3(8, 8, 32), 256>>>(img1, img2, buf1, buf2, sums);
    ssim_all_kernel<<<10912, dim3(32, 8)>>>(img1, img2, buf1, buf2, sums);
    finalize_kernel<<<1, 1>>>(sums, out);
}